// round 2
// baseline (speedup 1.0000x reference)
#include <cuda_runtime.h>
#include <stdint.h>

// Problem constants (fixed by the reference's setup_inputs)
#define NUM_GRAPHS 512
#define NPG        1024
#define KSEL       512
#define NTOT       (NUM_GRAPHS * NPG)     // 524288 nodes
#define NSEL       (NUM_GRAPHS * KSEL)    // 262144 selected
#define C_DIM      64
#define NEDGE      8388608                // 16 * NTOT

// Output layout (float32, concatenated reference outputs:
// x_sel [NSEL,64] | new_edge_index [2,NEDGE] | batch_sel [NSEL] | perm [NSEL])
#define X_OFF      0ll
#define EDGE_OFF   16777216ll             // NSEL * C_DIM
#define BATCH_OFF  33554432ll             // EDGE_OFF + 2*NEDGE
#define PERM_OFF   33816576ll             // BATCH_OFF + NSEL

// Scratch (static device globals — no allocation)
__device__ int g_perm[NSEL];
__device__ int g_mask[NTOT];
__device__ int g_is64;

__device__ __forceinline__ uint32_t rotl32(uint32_t x, int r) {
    return __funnelshift_l(x, x, r);
}

// Threefry-2x32, 20 rounds — bit-exact match of jax._src.prng.threefry2x32
__device__ __forceinline__ void threefry(uint32_t k0, uint32_t k1,
                                         uint32_t x0, uint32_t x1,
                                         uint32_t& o0, uint32_t& o1) {
    uint32_t k2 = k0 ^ k1 ^ 0x1BD11BDAu;
    x0 += k0; x1 += k1;
#define TF_R(r) { x0 += x1; x1 = rotl32(x1, (r)); x1 ^= x0; }
    TF_R(13) TF_R(15) TF_R(26) TF_R(6)   x0 += k1; x1 += k2 + 1u;
    TF_R(17) TF_R(29) TF_R(16) TF_R(24)  x0 += k2; x1 += k0 + 2u;
    TF_R(13) TF_R(15) TF_R(26) TF_R(6)   x0 += k0; x1 += k1 + 3u;
    TF_R(17) TF_R(29) TF_R(16) TF_R(24)  x0 += k1; x1 += k2 + 4u;
    TF_R(13) TF_R(15) TF_R(26) TF_R(6)   x0 += k2; x1 += k0 + 5u;
#undef TF_R
    o0 = x0; o1 = x1;
}

__global__ void init_mask_kernel() {
    int i = blockIdx.x * blockDim.x + threadIdx.x;
    if (i < NTOT) g_mask[i] = -1;
}

// Detect whether edge_index is int64 (odd 32-bit words all zero) or int32.
__global__ void detect_kernel(const unsigned int* __restrict__ e) {
    __shared__ unsigned int acc[256];
    unsigned int v = 0;
    for (int i = threadIdx.x; i < 4096; i += 256) v |= e[2 * i + 1];
    acc[threadIdx.x] = v;
    __syncthreads();
    for (int s = 128; s > 0; s >>= 1) {
        if (threadIdx.x < s) acc[threadIdx.x] |= acc[threadIdx.x + s];
        __syncthreads();
    }
    if (threadIdx.x == 0) g_is64 = (acc[0] == 0u) ? 1 : 0;
}

// One block per graph: generate 1024 threefry sort keys, stable-sort
// arange(1024) by them, keep first 512, sort ascending, emit outputs.
__global__ __launch_bounds__(NPG) void select_kernel(float* __restrict__ out) {
    __shared__ unsigned long long kv[NPG];
    __shared__ unsigned int sel[KSEL];
    const int g = blockIdx.x;
    const int t = threadIdx.x;

    // key_g = threefry((0,42), (0,g)) ; subkey = threefry(key_g, (0,1))
    uint32_t a0, a1, b0, b1, c0, c1;
    threefry(0u, 42u, 0u, (uint32_t)g, a0, a1);
    threefry(a0, a1, 0u, 1u, b0, b1);
    threefry(b0, b1, 0u, (uint32_t)t, c0, c1);
    uint32_t sk = c0 ^ c1;  // 32-bit random bits = o0 ^ o1

    kv[t] = ((unsigned long long)sk << 32) | (unsigned long long)t;
    __syncthreads();

    // Bitonic sort ascending, 1024 elems, 1024 threads (stable via idx tiebreak)
    for (int k = 2; k <= NPG; k <<= 1) {
        for (int j = k >> 1; j > 0; j >>= 1) {
            int ixj = t ^ j;
            if (ixj > t) {
                unsigned long long va = kv[t], vb = kv[ixj];
                bool up = ((t & k) == 0);
                if ((va > vb) == up) { kv[t] = vb; kv[ixj] = va; }
            }
            __syncthreads();
        }
    }

    // First 512 entries = selected local node ids; sort them ascending
    if (t < KSEL) sel[t] = (unsigned int)(kv[t] & 0xFFFFFFFFu);
    __syncthreads();

    for (int k = 2; k <= KSEL; k <<= 1) {
        for (int j = k >> 1; j > 0; j >>= 1) {
            int ixj = t ^ j;
            if (ixj > t && ixj < KSEL) {
                unsigned int va = sel[t], vb = sel[ixj];
                bool up = ((t & k) == 0);
                if ((va > vb) == up) { sel[t] = vb; sel[ixj] = va; }
            }
            __syncthreads();
        }
    }

    if (t < KSEL) {
        int local  = (int)sel[t];
        int global = g * NPG + local;
        int tg     = g * KSEL + t;
        g_perm[tg]     = global;
        g_mask[global] = tg;
        out[BATCH_OFF + tg] = (float)g;
        out[PERM_OFF  + tg] = (float)global;
    }
}

// x_sel gather: one float4 per thread, rows of 64 floats = 16 float4
__global__ void gather_kernel(const float4* __restrict__ x, float4* __restrict__ out) {
    int i = blockIdx.x * blockDim.x + threadIdx.x;  // over NSEL*16
    int row = i >> 4;
    int c   = i & 15;
    int src = g_perm[row];
    out[(long long)row * 16 + c] = x[(long long)src * 16 + c];
}

// Edge filter: relabel via mask, drop edges touching removed nodes (-1).
// Handles 4 edges per thread; dtype of edge_index decided by g_is64.
__global__ void edge_kernel(const unsigned int* __restrict__ eidx,
                            float4* __restrict__ outr,
                            float4* __restrict__ outc) {
    int i = blockIdx.x * blockDim.x + threadIdx.x;  // over NEDGE/4
    int n[4], m[4];
    if (g_is64) {
        // int64 layout: row stride = NEDGE*8 bytes = NEDGE/2 int4
        const int4* p = (const int4*)eidx;
        int4 a = p[2 * i], b = p[2 * i + 1];
        n[0] = a.x; n[1] = a.z; n[2] = b.x; n[3] = b.z;
        const int4* q = p + (NEDGE / 2);
        int4 c = q[2 * i], d = q[2 * i + 1];
        m[0] = c.x; m[1] = c.z; m[2] = d.x; m[3] = d.z;
    } else {
        // int32 layout: row stride = NEDGE*4 bytes = NEDGE/4 int4
        const int4* p = (const int4*)eidx;
        int4 a = p[i];
        n[0] = a.x; n[1] = a.y; n[2] = a.z; n[3] = a.w;
        const int4* q = p + (NEDGE / 4);
        int4 c = q[i];
        m[0] = c.x; m[1] = c.y; m[2] = c.z; m[3] = c.w;
    }
    float rr[4], cc[4];
#pragma unroll
    for (int j = 0; j < 4; j++) {
        unsigned un = (unsigned)n[j], um = (unsigned)m[j];
        int rn = (un < NTOT) ? g_mask[un] : -1;
        int cm = (um < NTOT) ? g_mask[um] : -1;
        bool keep = (rn >= 0) & (cm >= 0);
        rr[j] = keep ? (float)rn : -1.0f;
        cc[j] = keep ? (float)cm : -1.0f;
    }
    outr[i] = make_float4(rr[0], rr[1], rr[2], rr[3]);
    outc[i] = make_float4(cc[0], cc[1], cc[2], cc[3]);
}

extern "C" void kernel_launch(void* const* d_in, const int* in_sizes, int n_in,
                              void* d_out, int out_size) {
    const float* x        = (const float*)d_in[0];
    const unsigned int* e = (const unsigned int*)d_in[1];
    float* out            = (float*)d_out;

    // 0) dtype sniff for edge_index (int32 vs int64)
    detect_kernel<<<1, 256>>>(e);

    // 1) mask = -1
    init_mask_kernel<<<(NTOT + 255) / 256, 256>>>();

    // 2) per-graph random selection + mask/perm/batch outputs
    select_kernel<<<NUM_GRAPHS, NPG>>>(out);

    // 3) x_sel gather
    gather_kernel<<<(NSEL * 16) / 256, 256>>>((const float4*)x,
                                              (float4*)(out + X_OFF));

    // 4) edge relabel/filter
    edge_kernel<<<(NEDGE / 4) / 256, 256>>>(
        e,
        (float4*)(out + EDGE_OFF),
        (float4*)(out + EDGE_OFF + NEDGE));
}

// round 3
// speedup vs baseline: 1.8500x; 1.8500x over previous
#include <cuda_runtime.h>
#include <stdint.h>

// Problem constants (fixed by the reference's setup_inputs)
#define NUM_GRAPHS 512
#define NPG        1024
#define KSEL       512
#define NTOT       (NUM_GRAPHS * NPG)     // 524288 nodes
#define NSEL       (NUM_GRAPHS * KSEL)    // 262144 selected
#define NEDGE      8388608                // 16 * NTOT

// Output layout (float32, concatenated reference outputs:
// x_sel [NSEL,64] | new_edge_index [2,NEDGE] | batch_sel [NSEL] | perm [NSEL])
#define X_OFF      0ll
#define EDGE_OFF   16777216ll             // NSEL * 64
#define BATCH_OFF  33554432ll             // EDGE_OFF + 2*NEDGE
#define PERM_OFF   33816576ll             // BATCH_OFF + NSEL

#define GATHER_BLOCKS 8192                // NSEL*16/2 float4-pairs / 256
#define EDGE_BLOCKS   4096                // NEDGE/8 / 256

// Scratch (static device globals — no allocation)
__device__ int   g_perm[NSEL];
__device__ uint2 g_lut[NTOT / 32];        // {ballot bits, global rank base} per 32 nodes
__device__ int   g_is64;

__device__ __forceinline__ uint32_t rotl32(uint32_t x, int r) {
    return __funnelshift_l(x, x, r);
}

// Threefry-2x32, 20 rounds — bit-exact match of jax._src.prng.threefry2x32
__device__ __forceinline__ void threefry(uint32_t k0, uint32_t k1,
                                         uint32_t x0, uint32_t x1,
                                         uint32_t& o0, uint32_t& o1) {
    uint32_t k2 = k0 ^ k1 ^ 0x1BD11BDAu;
    x0 += k0; x1 += k1;
#define TF_R(r) { x0 += x1; x1 = rotl32(x1, (r)); x1 ^= x0; }
    TF_R(13) TF_R(15) TF_R(26) TF_R(6)   x0 += k1; x1 += k2 + 1u;
    TF_R(17) TF_R(29) TF_R(16) TF_R(24)  x0 += k2; x1 += k0 + 2u;
    TF_R(13) TF_R(15) TF_R(26) TF_R(6)   x0 += k0; x1 += k1 + 3u;
    TF_R(17) TF_R(29) TF_R(16) TF_R(24)  x0 += k1; x1 += k2 + 4u;
    TF_R(13) TF_R(15) TF_R(26) TF_R(6)   x0 += k2; x1 += k0 + 5u;
#undef TF_R
    o0 = x0; o1 = x1;
}

// Detect whether edge_index is int64 (odd 32-bit words all zero) or int32.
__global__ void detect_kernel(const unsigned int* __restrict__ e) {
    __shared__ unsigned int acc[256];
    unsigned int v = 0;
    for (int i = threadIdx.x; i < 4096; i += 256) v |= e[2 * i + 1];
    acc[threadIdx.x] = v;
    __syncthreads();
    for (int s = 128; s > 0; s >>= 1) {
        if (threadIdx.x < s) acc[threadIdx.x] |= acc[threadIdx.x + s];
        __syncthreads();
    }
    if (threadIdx.x == 0) g_is64 = (acc[0] == 0u) ? 1 : 0;
}

// One block per graph. Select = the 512 entries with smallest stable composite
// (threefry_key << 32 | idx), found by 1024-bucket radix select + exact tie
// resolution. Rank within selection = prefix-popcount (final order is by idx).
__global__ __launch_bounds__(NPG) void select_kernel(float* __restrict__ out) {
    __shared__ unsigned int counts[1024];
    __shared__ unsigned int excl[1024];
    __shared__ unsigned int waux[32];
    __shared__ unsigned int woff[32];
    __shared__ unsigned int sThresh[2];       // [0]=T bucket, [1]=R
    __shared__ unsigned int sNT;
    __shared__ unsigned long long list[1024]; // threshold-bucket composites

    const int g = blockIdx.x;
    const int t = threadIdx.x;
    const int w = t >> 5;
    const int lane = t & 31;

    // key_g = threefry((0,42),(0,g)); subkey = threefry(key_g,(0,1));
    // bits[t] = o0^o1 of threefry(subkey,(0,t))
    uint32_t a0, a1, b0, b1, c0, c1;
    threefry(0u, 42u, 0u, (uint32_t)g, a0, a1);
    threefry(a0, a1, 0u, 1u, b0, b1);
    threefry(b0, b1, 0u, (uint32_t)t, c0, c1);
    const uint32_t sk = c0 ^ c1;
    const unsigned long long ckey =
        ((unsigned long long)sk << 32) | (unsigned long long)t;
    const unsigned int bucket = sk >> 22;     // top 10 bits

    counts[t] = 0;
    if (t == 0) sNT = 0;
    __syncthreads();
    atomicAdd(&counts[bucket], 1u);
    __syncthreads();

    // Block exclusive scan over counts[1024]
    {
        unsigned int v = counts[t];
        unsigned int inc = v;
#pragma unroll
        for (int d = 1; d < 32; d <<= 1) {
            unsigned int n_ = __shfl_up_sync(0xFFFFFFFFu, inc, d);
            if (lane >= d) inc += n_;
        }
        if (lane == 31) waux[w] = inc;
        __syncthreads();
        if (w == 0) {
            unsigned int s = waux[lane];
            unsigned int si = s;
#pragma unroll
            for (int d = 1; d < 32; d <<= 1) {
                unsigned int n_ = __shfl_up_sync(0xFFFFFFFFu, si, d);
                if (lane >= d) si += n_;
            }
            woff[lane] = si - s;              // exclusive
        }
        __syncthreads();
        excl[t] = woff[w] + inc - v;
    }
    __syncthreads();

    // Threshold bucket T contains order index 511; R = #selected within T
    {
        unsigned int e0 = excl[t], c = counts[t];
        if (e0 <= 511u && 511u < e0 + c) {
            sThresh[0] = (unsigned int)t;
            sThresh[1] = 512u - e0;           // 1..c
        }
    }
    __syncthreads();
    const unsigned int T = sThresh[0];
    const unsigned int R = sThresh[1];

    // Compact threshold-bucket composites, then exact rank-compare
    unsigned int myPos = 0xFFFFFFFFu;
    if (bucket == T) {
        myPos = atomicAdd(&sNT, 1u);
        list[myPos] = ckey;
    }
    __syncthreads();
    bool sel;
    if (bucket < T) {
        sel = true;
    } else if (bucket > T) {
        sel = false;
    } else {
        const unsigned int nT = sNT;
        unsigned int rank = 0;
        for (unsigned int j = 0; j < nT; j++)
            rank += (list[j] < ckey) ? 1u : 0u;
        sel = (rank < R);
    }

    // Rank via ballot + warp-count scan; emit LUT, perm, batch, perm outputs
    const unsigned int word = __ballot_sync(0xFFFFFFFFu, sel);
    if (lane == 0) waux[w] = __popc(word);
    __syncthreads();
    if (w == 0) {
        unsigned int s = waux[lane];
        unsigned int si = s;
#pragma unroll
        for (int d = 1; d < 32; d <<= 1) {
            unsigned int n_ = __shfl_up_sync(0xFFFFFFFFu, si, d);
            if (lane >= d) si += n_;
        }
        woff[lane] = si - s;
    }
    __syncthreads();
    const unsigned int base = (unsigned int)g * KSEL + woff[w];
    if (lane == 0) g_lut[g * 32 + w] = make_uint2(word, base);
    if (sel) {
        const int rank = (int)base + __popc(word & ((1u << lane) - 1u));
        const int global = g * NPG + t;
        g_perm[rank] = global;
        out[BATCH_OFF + rank] = (float)g;
        out[PERM_OFF  + rank] = (float)global;
    }
}

// Relabel node id via bitmap LUT (131KB, L1-resident)
__device__ __forceinline__ int relabel(unsigned int n) {
    if (n >= NTOT) return -1;
    const uint2 L = __ldg(&g_lut[n >> 5]);
    const unsigned int b = n & 31u;
    if (!((L.x >> b) & 1u)) return -1;
    return (int)(L.y + __popc(L.x & ((1u << b) - 1u)));
}

// Fused: blocks [0,GATHER_BLOCKS) gather x rows; rest relabel/filter edges.
__global__ __launch_bounds__(256) void stream_kernel(
    const float4* __restrict__ x,
    const unsigned int* __restrict__ eidx,
    float4* __restrict__ xout,
    float4* __restrict__ outr,
    float4* __restrict__ outc) {
    if (blockIdx.x < GATHER_BLOCKS) {
        // 2 float4 per thread from the same source row (independent loads)
        const int i = blockIdx.x * 256 + threadIdx.x;   // 0 .. NSEL*8-1
        const int row = i >> 3;
        const int c = i & 7;
        const long long src = (long long)g_perm[row] * 16;
        const long long dst = (long long)row * 16;
        const float4 v0 = x[src + c];
        const float4 v1 = x[src + c + 8];
        xout[dst + c]     = v0;
        xout[dst + c + 8] = v1;
    } else {
        const int j = (blockIdx.x - GATHER_BLOCKS) * 256 + threadIdx.x;
        const int e0 = j * 8;                            // 8 edges per thread
        int n[8], m[8];
        const int4* p = (const int4*)eidx;
        if (g_is64) {
            const int4* q = p + (NEDGE / 2);
            int4 A[4], B[4];
#pragma unroll
            for (int k = 0; k < 4; k++) { A[k] = p[e0 / 2 + k]; B[k] = q[e0 / 2 + k]; }
#pragma unroll
            for (int k = 0; k < 4; k++) {
                n[2 * k] = A[k].x; n[2 * k + 1] = A[k].z;
                m[2 * k] = B[k].x; m[2 * k + 1] = B[k].z;
            }
        } else {
            const int4* q = p + (NEDGE / 4);
            int4 A0 = p[e0 / 4], A1 = p[e0 / 4 + 1];
            int4 B0 = q[e0 / 4], B1 = q[e0 / 4 + 1];
            n[0] = A0.x; n[1] = A0.y; n[2] = A0.z; n[3] = A0.w;
            n[4] = A1.x; n[5] = A1.y; n[6] = A1.z; n[7] = A1.w;
            m[0] = B0.x; m[1] = B0.y; m[2] = B0.z; m[3] = B0.w;
            m[4] = B1.x; m[5] = B1.y; m[6] = B1.z; m[7] = B1.w;
        }
        float rr[8], cc[8];
#pragma unroll
        for (int k = 0; k < 8; k++) {
            const int r = relabel((unsigned int)n[k]);
            const int c = relabel((unsigned int)m[k]);
            const bool keep = (r >= 0) & (c >= 0);
            rr[k] = keep ? (float)r : -1.0f;
            cc[k] = keep ? (float)c : -1.0f;
        }
        outr[e0 / 4]     = make_float4(rr[0], rr[1], rr[2], rr[3]);
        outr[e0 / 4 + 1] = make_float4(rr[4], rr[5], rr[6], rr[7]);
        outc[e0 / 4]     = make_float4(cc[0], cc[1], cc[2], cc[3]);
        outc[e0 / 4 + 1] = make_float4(cc[4], cc[5], cc[6], cc[7]);
    }
}

extern "C" void kernel_launch(void* const* d_in, const int* in_sizes, int n_in,
                              void* d_out, int out_size) {
    const float* x        = (const float*)d_in[0];
    const unsigned int* e = (const unsigned int*)d_in[1];
    float* out            = (float*)d_out;

    detect_kernel<<<1, 256>>>(e);
    select_kernel<<<NUM_GRAPHS, NPG>>>(out);
    stream_kernel<<<GATHER_BLOCKS + EDGE_BLOCKS, 256>>>(
        (const float4*)x, e,
        (float4*)(out + X_OFF),
        (float4*)(out + EDGE_OFF),
        (float4*)(out + EDGE_OFF + NEDGE));
}

// round 4
// speedup vs baseline: 2.0715x; 1.1197x over previous
#include <cuda_runtime.h>
#include <stdint.h>

// Problem constants (fixed by the reference's setup_inputs)
#define NUM_GRAPHS 512
#define NPG        1024
#define KSEL       512
#define NTOT       (NUM_GRAPHS * NPG)     // 524288 nodes
#define NSEL       (NUM_GRAPHS * KSEL)    // 262144 selected
#define NEDGE      8388608                // 16 * NTOT

// Output layout (float32, concatenated reference outputs:
// x_sel [NSEL,64] | new_edge_index [2,NEDGE] | batch_sel [NSEL] | perm [NSEL])
#define X_OFF      0ll
#define EDGE_OFF   16777216ll             // NSEL * 64
#define BATCH_OFF  33554432ll             // EDGE_OFF + 2*NEDGE
#define PERM_OFF   33816576ll             // BATCH_OFF + NSEL

#define GATHER_BLOCKS 8192                // NSEL*8 threads / 256
#define EDGE_BLOCKS   4096                // NEDGE/8 threads / 256

// Scratch (static device globals — no allocation)
__device__ int   g_perm[NSEL];
__device__ uint2 g_lut[NTOT / 32];        // {ballot bits, global rank base} per 32 nodes
__device__ int   g_is64;

__device__ __forceinline__ uint32_t rotl32(uint32_t x, int r) {
    return __funnelshift_l(x, x, r);
}

// Threefry-2x32, 20 rounds — bit-exact match of jax._src.prng.threefry2x32
__device__ __forceinline__ void threefry(uint32_t k0, uint32_t k1,
                                         uint32_t x0, uint32_t x1,
                                         uint32_t& o0, uint32_t& o1) {
    uint32_t k2 = k0 ^ k1 ^ 0x1BD11BDAu;
    x0 += k0; x1 += k1;
#define TF_R(r) { x0 += x1; x1 = rotl32(x1, (r)); x1 ^= x0; }
    TF_R(13) TF_R(15) TF_R(26) TF_R(6)   x0 += k1; x1 += k2 + 1u;
    TF_R(17) TF_R(29) TF_R(16) TF_R(24)  x0 += k2; x1 += k0 + 2u;
    TF_R(13) TF_R(15) TF_R(26) TF_R(6)   x0 += k0; x1 += k1 + 3u;
    TF_R(17) TF_R(29) TF_R(16) TF_R(24)  x0 += k1; x1 += k2 + 4u;
    TF_R(13) TF_R(15) TF_R(26) TF_R(6)   x0 += k2; x1 += k0 + 5u;
#undef TF_R
    o0 = x0; o1 = x1;
}

// One block per graph. Select = the 512 entries with smallest stable composite
// (threefry_key << 32 | idx), via 1024-bucket radix select + exact tie
// resolution in the threshold bucket. Rank = prefix-popcount (order is by idx).
// Block 0, warp 0 additionally sniffs edge_index dtype (int64 => odd words 0,
// since node ids < 2^19; int32 => odd words are random nonzero node ids).
__global__ __launch_bounds__(NPG) void select_kernel(float* __restrict__ out,
                                                     const unsigned int* __restrict__ e) {
    __shared__ unsigned int counts[1024];
    __shared__ unsigned int waux[32];
    __shared__ unsigned int woff[32];
    __shared__ unsigned int sThresh[2];       // [0]=T bucket, [1]=R
    __shared__ unsigned int sNT;
    __shared__ unsigned long long list[1024]; // threshold-bucket composites

    const int g = blockIdx.x;
    const int t = threadIdx.x;
    const int w = t >> 5;
    const int lane = t & 31;

    // dtype sniff (overlaps with threefry compute below)
    if (g == 0 && w == 0) {
        unsigned int v = e[2 * lane + 1] | e[2 * (lane + 32) + 1];
        unsigned int any = __ballot_sync(0xFFFFFFFFu, v != 0u);
        if (lane == 0) g_is64 = (any == 0u) ? 1 : 0;
    }

    // key_g = threefry((0,42),(0,g)); subkey = threefry(key_g,(0,1));
    // bits[t] = o0^o1 of threefry(subkey,(0,t))
    uint32_t a0, a1, b0, b1, c0, c1;
    threefry(0u, 42u, 0u, (uint32_t)g, a0, a1);
    threefry(a0, a1, 0u, 1u, b0, b1);
    threefry(b0, b1, 0u, (uint32_t)t, c0, c1);
    const uint32_t sk = c0 ^ c1;
    const unsigned long long ckey =
        ((unsigned long long)sk << 32) | (unsigned long long)t;
    const unsigned int bucket = sk >> 22;     // top 10 bits

    counts[t] = 0;
    if (t == 0) sNT = 0;
    __syncthreads();
    atomicAdd(&counts[bucket], 1u);
    __syncthreads();

    // Block exclusive scan over counts[1024]; find threshold bucket
    unsigned int myExcl;
    {
        unsigned int v = counts[t];
        unsigned int inc = v;
#pragma unroll
        for (int d = 1; d < 32; d <<= 1) {
            unsigned int n_ = __shfl_up_sync(0xFFFFFFFFu, inc, d);
            if (lane >= d) inc += n_;
        }
        if (lane == 31) waux[w] = inc;
        __syncthreads();
        if (w == 0) {
            unsigned int s = waux[lane];
            unsigned int si = s;
#pragma unroll
            for (int d = 1; d < 32; d <<= 1) {
                unsigned int n_ = __shfl_up_sync(0xFFFFFFFFu, si, d);
                if (lane >= d) si += n_;
            }
            woff[lane] = si - s;              // exclusive
        }
        __syncthreads();
        myExcl = woff[w] + inc - v;
        if (myExcl <= 511u && 511u < myExcl + v) {
            sThresh[0] = (unsigned int)t;
            sThresh[1] = 512u - myExcl;       // 1..v
        }
    }
    __syncthreads();
    const unsigned int T = sThresh[0];
    const unsigned int R = sThresh[1];

    // Compact threshold-bucket composites, then exact rank-compare
    if (bucket == T) {
        unsigned int pos = atomicAdd(&sNT, 1u);
        list[pos] = ckey;
    }
    __syncthreads();
    bool sel;
    if (bucket < T) {
        sel = true;
    } else if (bucket > T) {
        sel = false;
    } else {
        const unsigned int nT = sNT;
        unsigned int rank = 0;
        for (unsigned int j = 0; j < nT; j++)
            rank += (list[j] < ckey) ? 1u : 0u;
        sel = (rank < R);
    }

    // Rank via ballot + warp-count scan; emit LUT, perm, batch, perm outputs
    const unsigned int word = __ballot_sync(0xFFFFFFFFu, sel);
    if (lane == 0) waux[w] = __popc(word);
    __syncthreads();
    if (w == 0) {
        unsigned int s = waux[lane];
        unsigned int si = s;
#pragma unroll
        for (int d = 1; d < 32; d <<= 1) {
            unsigned int n_ = __shfl_up_sync(0xFFFFFFFFu, si, d);
            if (lane >= d) si += n_;
        }
        woff[lane] = si - s;
    }
    __syncthreads();
    const unsigned int base = (unsigned int)g * KSEL + woff[w];
    if (lane == 0) g_lut[g * 32 + w] = make_uint2(word, base);
    if (sel) {
        const int rank = (int)base + __popc(word & ((1u << lane) - 1u));
        const int global = g * NPG + t;
        g_perm[rank] = global;
        out[BATCH_OFF + rank] = (float)g;
        out[PERM_OFF  + rank] = (float)global;
    }
}

// Relabel node id via bitmap LUT (131KB, L1/L2-resident)
__device__ __forceinline__ int relabel(unsigned int n) {
    if (n >= NTOT) return -1;
    const uint2 L = __ldg(&g_lut[n >> 5]);
    const unsigned int b = n & 31u;
    if (!((L.x >> b) & 1u)) return -1;
    return (int)(L.y + __popc(L.x & ((1u << b) - 1u)));
}

// Fused: blocks [0,GATHER_BLOCKS) gather x rows; rest relabel/filter edges.
__global__ __launch_bounds__(256) void stream_kernel(
    const float4* __restrict__ x,
    const unsigned int* __restrict__ eidx,
    float4* __restrict__ xout,
    float4* __restrict__ outr,
    float4* __restrict__ outc) {
    if (blockIdx.x < GATHER_BLOCKS) {
        // 2 float4 per thread from the same source row (independent loads)
        const int i = blockIdx.x * 256 + threadIdx.x;   // 0 .. NSEL*8-1
        const int row = i >> 3;
        const int c = i & 7;
        const long long src = (long long)g_perm[row] * 16;
        const long long dst = (long long)row * 16;
        const float4 v0 = x[src + c];
        const float4 v1 = x[src + c + 8];
        xout[dst + c]     = v0;
        xout[dst + c + 8] = v1;
    } else {
        const int j = (blockIdx.x - GATHER_BLOCKS) * 256 + threadIdx.x;
        const int e0 = j * 8;                            // 8 edges per thread
        int n[8], m[8];
        const int4* p = (const int4*)eidx;
        if (g_is64) {
            const int4* q = p + (NEDGE / 2);
            int4 A[4], B[4];
#pragma unroll
            for (int k = 0; k < 4; k++) { A[k] = p[e0 / 2 + k]; B[k] = q[e0 / 2 + k]; }
#pragma unroll
            for (int k = 0; k < 4; k++) {
                n[2 * k] = A[k].x; n[2 * k + 1] = A[k].z;
                m[2 * k] = B[k].x; m[2 * k + 1] = B[k].z;
            }
        } else {
            const int4* q = p + (NEDGE / 4);
            int4 A0 = p[e0 / 4], A1 = p[e0 / 4 + 1];
            int4 B0 = q[e0 / 4], B1 = q[e0 / 4 + 1];
            n[0] = A0.x; n[1] = A0.y; n[2] = A0.z; n[3] = A0.w;
            n[4] = A1.x; n[5] = A1.y; n[6] = A1.z; n[7] = A1.w;
            m[0] = B0.x; m[1] = B0.y; m[2] = B0.z; m[3] = B0.w;
            m[4] = B1.x; m[5] = B1.y; m[6] = B1.z; m[7] = B1.w;
        }
        float rr[8], cc[8];
#pragma unroll
        for (int k = 0; k < 8; k++) {
            const int r = relabel((unsigned int)n[k]);
            const int c = relabel((unsigned int)m[k]);
            const bool keep = (r >= 0) & (c >= 0);
            rr[k] = keep ? (float)r : -1.0f;
            cc[k] = keep ? (float)c : -1.0f;
        }
        outr[e0 / 4]     = make_float4(rr[0], rr[1], rr[2], rr[3]);
        outr[e0 / 4 + 1] = make_float4(rr[4], rr[5], rr[6], rr[7]);
        outc[e0 / 4]     = make_float4(cc[0], cc[1], cc[2], cc[3]);
        outc[e0 / 4 + 1] = make_float4(cc[4], cc[5], cc[6], cc[7]);
    }
}

extern "C" void kernel_launch(void* const* d_in, const int* in_sizes, int n_in,
                              void* d_out, int out_size) {
    const float* x        = (const float*)d_in[0];
    const unsigned int* e = (const unsigned int*)d_in[1];
    float* out            = (float*)d_out;

    select_kernel<<<NUM_GRAPHS, NPG>>>(out, e);
    stream_kernel<<<GATHER_BLOCKS + EDGE_BLOCKS, 256>>>(
        (const float4*)x, e,
        (float4*)(out + X_OFF),
        (float4*)(out + EDGE_OFF),
        (float4*)(out + EDGE_OFF + NEDGE));
}

// round 5
// speedup vs baseline: 2.6173x; 1.2635x over previous
#include <cuda_runtime.h>
#include <stdint.h>

// Problem constants (fixed by the reference's setup_inputs)
#define NUM_GRAPHS 512
#define NPG        1024
#define KSEL       512
#define NTOT       (NUM_GRAPHS * NPG)     // 524288 nodes
#define NSEL       (NUM_GRAPHS * KSEL)    // 262144 selected
#define NEDGE      8388608                // 16 * NTOT

// Output layout (float32, concatenated reference outputs:
// x_sel [NSEL,64] | new_edge_index [2,NEDGE] | batch_sel [NSEL] | perm [NSEL])
#define X_OFF      0ll
#define EDGE_OFF   16777216ll             // NSEL * 64
#define BATCH_OFF  33554432ll             // EDGE_OFF + 2*NEDGE
#define PERM_OFF   33816576ll             // BATCH_OFF + NSEL

#define GATHER_BLOCKS 8192                // NSEL*8 threads / 256
#define EDGE_BLOCKS   4096                // NEDGE/8 threads / 256
#define TOTAL_BLOCKS  (GATHER_BLOCKS + EDGE_BLOCKS)

// Scratch (static device globals — no allocation)
__device__ int   g_perm[NSEL];
__device__ uint2 g_lut[NTOT / 32];        // {ballot bits, global rank base} per 32 nodes
__device__ int   g_is64;

__device__ __forceinline__ uint32_t rotl32(uint32_t x, int r) {
    return __funnelshift_l(x, x, r);
}

// Threefry-2x32, 20 rounds — bit-exact match of jax._src.prng.threefry2x32
__device__ __forceinline__ void threefry(uint32_t k0, uint32_t k1,
                                         uint32_t x0, uint32_t x1,
                                         uint32_t& o0, uint32_t& o1) {
    uint32_t k2 = k0 ^ k1 ^ 0x1BD11BDAu;
    x0 += k0; x1 += k1;
#define TF_R(r) { x0 += x1; x1 = rotl32(x1, (r)); x1 ^= x0; }
    TF_R(13) TF_R(15) TF_R(26) TF_R(6)   x0 += k1; x1 += k2 + 1u;
    TF_R(17) TF_R(29) TF_R(16) TF_R(24)  x0 += k2; x1 += k0 + 2u;
    TF_R(13) TF_R(15) TF_R(26) TF_R(6)   x0 += k0; x1 += k1 + 3u;
    TF_R(17) TF_R(29) TF_R(16) TF_R(24)  x0 += k1; x1 += k2 + 4u;
    TF_R(13) TF_R(15) TF_R(26) TF_R(6)   x0 += k2; x1 += k0 + 5u;
#undef TF_R
    o0 = x0; o1 = x1;
}

// One block per graph. Select = the 512 entries with smallest stable composite
// (threefry_key << 32 | idx), via 1024-bucket radix select + exact tie
// resolution in the threshold bucket. Rank = prefix-popcount (order is by idx).
// Block 0, warp 0 additionally sniffs edge_index dtype (int64 => odd words 0,
// since node ids < 2^19; int32 => odd words are random nonzero node ids).
__global__ __launch_bounds__(NPG) void select_kernel(float* __restrict__ out,
                                                     const unsigned int* __restrict__ e) {
    __shared__ unsigned int counts[1024];
    __shared__ unsigned int waux[32];
    __shared__ unsigned int woff[32];
    __shared__ unsigned int sThresh[2];       // [0]=T bucket, [1]=R
    __shared__ unsigned int sNT;
    __shared__ unsigned long long list[1024]; // threshold-bucket composites

    const int g = blockIdx.x;
    const int t = threadIdx.x;
    const int w = t >> 5;
    const int lane = t & 31;

    // dtype sniff (overlaps with threefry compute below)
    if (g == 0 && w == 0) {
        unsigned int v = e[2 * lane + 1] | e[2 * (lane + 32) + 1];
        unsigned int any = __ballot_sync(0xFFFFFFFFu, v != 0u);
        if (lane == 0) g_is64 = (any == 0u) ? 1 : 0;
    }

    // key_g = threefry((0,42),(0,g)); subkey = threefry(key_g,(0,1));
    // bits[t] = o0^o1 of threefry(subkey,(0,t))
    uint32_t a0, a1, b0, b1, c0, c1;
    threefry(0u, 42u, 0u, (uint32_t)g, a0, a1);
    threefry(a0, a1, 0u, 1u, b0, b1);
    threefry(b0, b1, 0u, (uint32_t)t, c0, c1);
    const uint32_t sk = c0 ^ c1;
    const unsigned long long ckey =
        ((unsigned long long)sk << 32) | (unsigned long long)t;
    const unsigned int bucket = sk >> 22;     // top 10 bits

    counts[t] = 0;
    if (t == 0) sNT = 0;
    __syncthreads();
    atomicAdd(&counts[bucket], 1u);
    __syncthreads();

    // Block exclusive scan over counts[1024]; find threshold bucket
    {
        unsigned int v = counts[t];
        unsigned int inc = v;
#pragma unroll
        for (int d = 1; d < 32; d <<= 1) {
            unsigned int n_ = __shfl_up_sync(0xFFFFFFFFu, inc, d);
            if (lane >= d) inc += n_;
        }
        if (lane == 31) waux[w] = inc;
        __syncthreads();
        if (w == 0) {
            unsigned int s = waux[lane];
            unsigned int si = s;
#pragma unroll
            for (int d = 1; d < 32; d <<= 1) {
                unsigned int n_ = __shfl_up_sync(0xFFFFFFFFu, si, d);
                if (lane >= d) si += n_;
            }
            woff[lane] = si - s;              // exclusive
        }
        __syncthreads();
        unsigned int myExcl = woff[w] + inc - v;
        if (myExcl <= 511u && 511u < myExcl + v) {
            sThresh[0] = (unsigned int)t;
            sThresh[1] = 512u - myExcl;       // 1..v
        }
    }
    __syncthreads();
    const unsigned int T = sThresh[0];
    const unsigned int R = sThresh[1];

    // Compact threshold-bucket composites, then exact rank-compare
    if (bucket == T) {
        unsigned int pos = atomicAdd(&sNT, 1u);
        list[pos] = ckey;
    }
    __syncthreads();
    bool sel;
    if (bucket < T) {
        sel = true;
    } else if (bucket > T) {
        sel = false;
    } else {
        const unsigned int nT = sNT;
        unsigned int rank = 0;
        for (unsigned int j = 0; j < nT; j++)
            rank += (list[j] < ckey) ? 1u : 0u;
        sel = (rank < R);
    }

    // Rank via ballot + warp-count scan; emit LUT, perm, batch, perm outputs
    const unsigned int word = __ballot_sync(0xFFFFFFFFu, sel);
    if (lane == 0) waux[w] = __popc(word);
    __syncthreads();
    if (w == 0) {
        unsigned int s = waux[lane];
        unsigned int si = s;
#pragma unroll
        for (int d = 1; d < 32; d <<= 1) {
            unsigned int n_ = __shfl_up_sync(0xFFFFFFFFu, si, d);
            if (lane >= d) si += n_;
        }
        woff[lane] = si - s;
    }
    __syncthreads();
    const unsigned int base = (unsigned int)g * KSEL + woff[w];
    if (lane == 0) g_lut[g * 32 + w] = make_uint2(word, base);
    if (sel) {
        const int rank = (int)base + __popc(word & ((1u << lane) - 1u));
        const int global = g * NPG + t;
        g_perm[rank] = global;
        out[BATCH_OFF + rank] = (float)g;
        out[PERM_OFF  + rank] = (float)global;
    }
}

// Relabel node id via bitmap LUT (131KB; kept L1-resident — streaming
// accesses use evict-first policy so they don't displace it)
__device__ __forceinline__ int relabel(unsigned int n) {
    if (n >= NTOT) return -1;
    const uint2 L = __ldg(&g_lut[n >> 5]);
    const unsigned int b = n & 31u;
    if (!((L.x >> b) & 1u)) return -1;
    return (int)(L.y + __popc(L.x & ((1u << b) - 1u)));
}

// Fused: blocks interleaved 2:1 gather:edge so BW-bound gather waves overlap
// latency-bound edge waves. All streaming traffic uses .cs (evict-first).
__global__ __launch_bounds__(256) void stream_kernel(
    const float4* __restrict__ x,
    const unsigned int* __restrict__ eidx,
    float4* __restrict__ xout,
    float4* __restrict__ outr,
    float4* __restrict__ outc) {
    const unsigned int b = blockIdx.x;
    const unsigned int phase = b % 3u;     // 0,1 => gather; 2 => edge
    if (phase != 2u) {
        const int gb = (int)(b / 3u) * 2 + (int)phase;   // 0..GATHER_BLOCKS-1
        // 2 float4 per thread from the same source row (independent loads)
        const int i = gb * 256 + threadIdx.x;            // 0 .. NSEL*8-1
        const int row = i >> 3;
        const int c = i & 7;
        const long long src = (long long)__ldg(&g_perm[row]) * 16;
        const long long dst = (long long)row * 16;
        const float4 v0 = __ldcs(&x[src + c]);
        const float4 v1 = __ldcs(&x[src + c + 8]);
        __stcs(&xout[dst + c],     v0);
        __stcs(&xout[dst + c + 8], v1);
    } else {
        const int eb = (int)(b / 3u);                    // 0..EDGE_BLOCKS-1
        const int j = eb * 256 + threadIdx.x;
        const int e0 = j * 8;                            // 8 edges per thread
        int n[8], m[8];
        const int4* p = (const int4*)eidx;
        if (g_is64) {
            const int4* q = p + (NEDGE / 2);
            int4 A[4], B[4];
#pragma unroll
            for (int k = 0; k < 4; k++) { A[k] = __ldcs(&p[e0 / 2 + k]); B[k] = __ldcs(&q[e0 / 2 + k]); }
#pragma unroll
            for (int k = 0; k < 4; k++) {
                n[2 * k] = A[k].x; n[2 * k + 1] = A[k].z;
                m[2 * k] = B[k].x; m[2 * k + 1] = B[k].z;
            }
        } else {
            const int4* q = p + (NEDGE / 4);
            int4 A0 = __ldcs(&p[e0 / 4]), A1 = __ldcs(&p[e0 / 4 + 1]);
            int4 B0 = __ldcs(&q[e0 / 4]), B1 = __ldcs(&q[e0 / 4 + 1]);
            n[0] = A0.x; n[1] = A0.y; n[2] = A0.z; n[3] = A0.w;
            n[4] = A1.x; n[5] = A1.y; n[6] = A1.z; n[7] = A1.w;
            m[0] = B0.x; m[1] = B0.y; m[2] = B0.z; m[3] = B0.w;
            m[4] = B1.x; m[5] = B1.y; m[6] = B1.z; m[7] = B1.w;
        }
        float rr[8], cc[8];
#pragma unroll
        for (int k = 0; k < 8; k++) {
            const int r = relabel((unsigned int)n[k]);
            const int c = relabel((unsigned int)m[k]);
            const bool keep = (r >= 0) & (c >= 0);
            rr[k] = keep ? (float)r : -1.0f;
            cc[k] = keep ? (float)c : -1.0f;
        }
        __stcs(&outr[e0 / 4],     make_float4(rr[0], rr[1], rr[2], rr[3]));
        __stcs(&outr[e0 / 4 + 1], make_float4(rr[4], rr[5], rr[6], rr[7]));
        __stcs(&outc[e0 / 4],     make_float4(cc[0], cc[1], cc[2], cc[3]));
        __stcs(&outc[e0 / 4 + 1], make_float4(cc[4], cc[5], cc[6], cc[7]));
    }
}

extern "C" void kernel_launch(void* const* d_in, const int* in_sizes, int n_in,
                              void* d_out, int out_size) {
    const float* x        = (const float*)d_in[0];
    const unsigned int* e = (const unsigned int*)d_in[1];
    float* out            = (float*)d_out;

    select_kernel<<<NUM_GRAPHS, NPG>>>(out, e);
    stream_kernel<<<TOTAL_BLOCKS, 256>>>(
        (const float4*)x, e,
        (float4*)(out + X_OFF),
        (float4*)(out + EDGE_OFF),
        (float4*)(out + EDGE_OFF + NEDGE));
}

// round 6
// speedup vs baseline: 2.7160x; 1.0377x over previous
#include <cuda_runtime.h>
#include <stdint.h>

// Problem constants (fixed by the reference's setup_inputs)
#define NUM_GRAPHS 512
#define NPG        1024
#define KSEL       512
#define NTOT       (NUM_GRAPHS * NPG)     // 524288 nodes
#define NSEL       (NUM_GRAPHS * KSEL)    // 262144 selected
#define NEDGE      8388608                // 16 * NTOT

// Output layout (float32, concatenated reference outputs:
// x_sel [NSEL,64] | new_edge_index [2,NEDGE] | batch_sel [NSEL] | perm [NSEL])
#define X_OFF      0ll
#define EDGE_OFF   16777216ll             // NSEL * 64
#define BATCH_OFF  33554432ll             // EDGE_OFF + 2*NEDGE
#define PERM_OFF   33816576ll             // BATCH_OFF + NSEL

#define LUT_WORDS     (NTOT / 32)         // 16384 uint2 = 131072 B
#define LUT_BYTES     (LUT_WORDS * 8)

#define GATHER_CHUNKS 2048                // NSEL*8 threads / 1024
#define EDGE_CHUNKS   1024                // NEDGE/8 threads / 1024
#define TOTAL_CHUNKS  (GATHER_CHUNKS + EDGE_CHUNKS)
#define STREAM_GRID   152                 // one resident block per SM (GB300)

// Scratch (static device globals — no allocation)
__device__ int   g_perm[NSEL];
__device__ uint2 g_lut[LUT_WORDS];        // {ballot bits, global rank base} per 32 nodes
__device__ int   g_is64;

__device__ __forceinline__ uint32_t rotl32(uint32_t x, int r) {
    return __funnelshift_l(x, x, r);
}

// Threefry-2x32, 20 rounds — bit-exact match of jax._src.prng.threefry2x32
__device__ __forceinline__ void threefry(uint32_t k0, uint32_t k1,
                                         uint32_t x0, uint32_t x1,
                                         uint32_t& o0, uint32_t& o1) {
    uint32_t k2 = k0 ^ k1 ^ 0x1BD11BDAu;
    x0 += k0; x1 += k1;
#define TF_R(r) { x0 += x1; x1 = rotl32(x1, (r)); x1 ^= x0; }
    TF_R(13) TF_R(15) TF_R(26) TF_R(6)   x0 += k1; x1 += k2 + 1u;
    TF_R(17) TF_R(29) TF_R(16) TF_R(24)  x0 += k2; x1 += k0 + 2u;
    TF_R(13) TF_R(15) TF_R(26) TF_R(6)   x0 += k0; x1 += k1 + 3u;
    TF_R(17) TF_R(29) TF_R(16) TF_R(24)  x0 += k1; x1 += k2 + 4u;
    TF_R(13) TF_R(15) TF_R(26) TF_R(6)   x0 += k2; x1 += k0 + 5u;
#undef TF_R
    o0 = x0; o1 = x1;
}

// One block per graph. Select = the 512 entries with smallest stable composite
// (threefry_key << 32 | idx), via 1024-bucket radix select + exact tie
// resolution in the threshold bucket. Rank = prefix-popcount (order is by idx).
// Block 0, warp 0 additionally sniffs edge_index dtype (int64 => odd words 0,
// since node ids < 2^19; int32 => odd words are random nonzero node ids).
__global__ __launch_bounds__(NPG) void select_kernel(float* __restrict__ out,
                                                     const unsigned int* __restrict__ e) {
    __shared__ unsigned int counts[1024];
    __shared__ unsigned int waux[32];
    __shared__ unsigned int woff[32];
    __shared__ unsigned int sThresh[2];       // [0]=T bucket, [1]=R
    __shared__ unsigned int sNT;
    __shared__ unsigned long long list[1024]; // threshold-bucket composites

    const int g = blockIdx.x;
    const int t = threadIdx.x;
    const int w = t >> 5;
    const int lane = t & 31;

    // dtype sniff (overlaps with threefry compute below)
    if (g == 0 && w == 0) {
        unsigned int v = e[2 * lane + 1] | e[2 * (lane + 32) + 1];
        unsigned int any = __ballot_sync(0xFFFFFFFFu, v != 0u);
        if (lane == 0) g_is64 = (any == 0u) ? 1 : 0;
    }

    // key_g = threefry((0,42),(0,g)); subkey = threefry(key_g,(0,1));
    // bits[t] = o0^o1 of threefry(subkey,(0,t))
    uint32_t a0, a1, b0, b1, c0, c1;
    threefry(0u, 42u, 0u, (uint32_t)g, a0, a1);
    threefry(a0, a1, 0u, 1u, b0, b1);
    threefry(b0, b1, 0u, (uint32_t)t, c0, c1);
    const uint32_t sk = c0 ^ c1;
    const unsigned long long ckey =
        ((unsigned long long)sk << 32) | (unsigned long long)t;
    const unsigned int bucket = sk >> 22;     // top 10 bits

    counts[t] = 0;
    if (t == 0) sNT = 0;
    __syncthreads();
    atomicAdd(&counts[bucket], 1u);
    __syncthreads();

    // Block exclusive scan over counts[1024]; find threshold bucket
    {
        unsigned int v = counts[t];
        unsigned int inc = v;
#pragma unroll
        for (int d = 1; d < 32; d <<= 1) {
            unsigned int n_ = __shfl_up_sync(0xFFFFFFFFu, inc, d);
            if (lane >= d) inc += n_;
        }
        if (lane == 31) waux[w] = inc;
        __syncthreads();
        if (w == 0) {
            unsigned int s = waux[lane];
            unsigned int si = s;
#pragma unroll
            for (int d = 1; d < 32; d <<= 1) {
                unsigned int n_ = __shfl_up_sync(0xFFFFFFFFu, si, d);
                if (lane >= d) si += n_;
            }
            woff[lane] = si - s;              // exclusive
        }
        __syncthreads();
        unsigned int myExcl = woff[w] + inc - v;
        if (myExcl <= 511u && 511u < myExcl + v) {
            sThresh[0] = (unsigned int)t;
            sThresh[1] = 512u - myExcl;       // 1..v
        }
    }
    __syncthreads();
    const unsigned int T = sThresh[0];
    const unsigned int R = sThresh[1];

    // Compact threshold-bucket composites, then exact rank-compare
    if (bucket == T) {
        unsigned int pos = atomicAdd(&sNT, 1u);
        list[pos] = ckey;
    }
    __syncthreads();
    bool sel;
    if (bucket < T) {
        sel = true;
    } else if (bucket > T) {
        sel = false;
    } else {
        const unsigned int nT = sNT;
        unsigned int rank = 0;
        for (unsigned int j = 0; j < nT; j++)
            rank += (list[j] < ckey) ? 1u : 0u;
        sel = (rank < R);
    }

    // Rank via ballot + warp-count scan; emit LUT, perm, batch, perm outputs
    const unsigned int word = __ballot_sync(0xFFFFFFFFu, sel);
    if (lane == 0) waux[w] = __popc(word);
    __syncthreads();
    if (w == 0) {
        unsigned int s = waux[lane];
        unsigned int si = s;
#pragma unroll
        for (int d = 1; d < 32; d <<= 1) {
            unsigned int n_ = __shfl_up_sync(0xFFFFFFFFu, si, d);
            if (lane >= d) si += n_;
        }
        woff[lane] = si - s;
    }
    __syncthreads();
    const unsigned int base = (unsigned int)g * KSEL + woff[w];
    if (lane == 0) g_lut[g * 32 + w] = make_uint2(word, base);
    if (sel) {
        const int rank = (int)base + __popc(word & ((1u << lane) - 1u));
        const int global = g * NPG + t;
        g_perm[rank] = global;
        out[BATCH_OFF + rank] = (float)g;
        out[PERM_OFF  + rank] = (float)global;
    }
}

// Relabel node id via shared-memory bitmap LUT
__device__ __forceinline__ int relabel_s(const uint2* __restrict__ lut,
                                         unsigned int n) {
    if (n >= NTOT) return -1;
    const uint2 L = lut[n >> 5];
    const unsigned int b = n & 31u;
    if (!((L.x >> b) & 1u)) return -1;
    return (int)(L.y + __popc(L.x & ((1u << b) - 1u)));
}

// Persistent fused kernel: each block stages the 131KB LUT in shared memory,
// then grid-strides over 3072 chunks interleaved 2 gather : 1 edge.
// All streaming traffic uses .cs (evict-first) so L2 keeps edge reuse.
__global__ __launch_bounds__(1024) void stream_kernel(
    const float4* __restrict__ x,
    const unsigned int* __restrict__ eidx,
    float4* __restrict__ xout,
    float4* __restrict__ outr,
    float4* __restrict__ outc) {
    extern __shared__ uint2 slut[];

    // Stage LUT: 8192 uint4 loads spread over 1024 threads
    {
        const uint4* src = (const uint4*)g_lut;
        uint4* dst = (uint4*)slut;
#pragma unroll
        for (int k = 0; k < 8; k++)
            dst[k * 1024 + threadIdx.x] = __ldg(&src[k * 1024 + threadIdx.x]);
    }
    __syncthreads();

    const int tid = threadIdx.x;
    const bool is64 = (g_is64 != 0);

    for (unsigned int c = blockIdx.x; c < TOTAL_CHUNKS; c += gridDim.x) {
        const unsigned int phase = c % 3u;     // 0,1 => gather; 2 => edge
        if (phase != 2u) {
            const int gb = (int)(c / 3u) * 2 + (int)phase;   // 0..GATHER_CHUNKS-1
            const int i = gb * 1024 + tid;                   // 0 .. NSEL*8-1
            const int row = i >> 3;
            const int cc = i & 7;
            const long long src = (long long)__ldg(&g_perm[row]) * 16;
            const long long dst = (long long)row * 16;
            const float4 v0 = __ldcs(&x[src + cc]);
            const float4 v1 = __ldcs(&x[src + cc + 8]);
            __stcs(&xout[dst + cc],     v0);
            __stcs(&xout[dst + cc + 8], v1);
        } else {
            const int eb = (int)(c / 3u);                    // 0..EDGE_CHUNKS-1
            const int j = eb * 1024 + tid;
            const int e0 = j * 8;                            // 8 edges per thread
            int n[8], m[8];
            const int4* p = (const int4*)eidx;
            if (is64) {
                const int4* q = p + (NEDGE / 2);
                int4 A[4], B[4];
#pragma unroll
                for (int k = 0; k < 4; k++) {
                    A[k] = __ldcs(&p[e0 / 2 + k]);
                    B[k] = __ldcs(&q[e0 / 2 + k]);
                }
#pragma unroll
                for (int k = 0; k < 4; k++) {
                    n[2 * k] = A[k].x; n[2 * k + 1] = A[k].z;
                    m[2 * k] = B[k].x; m[2 * k + 1] = B[k].z;
                }
            } else {
                const int4* q = p + (NEDGE / 4);
                int4 A0 = __ldcs(&p[e0 / 4]), A1 = __ldcs(&p[e0 / 4 + 1]);
                int4 B0 = __ldcs(&q[e0 / 4]), B1 = __ldcs(&q[e0 / 4 + 1]);
                n[0] = A0.x; n[1] = A0.y; n[2] = A0.z; n[3] = A0.w;
                n[4] = A1.x; n[5] = A1.y; n[6] = A1.z; n[7] = A1.w;
                m[0] = B0.x; m[1] = B0.y; m[2] = B0.z; m[3] = B0.w;
                m[4] = B1.x; m[5] = B1.y; m[6] = B1.z; m[7] = B1.w;
            }
            float rr[8], cc2[8];
#pragma unroll
            for (int k = 0; k < 8; k++) {
                const int r = relabel_s(slut, (unsigned int)n[k]);
                const int cl = relabel_s(slut, (unsigned int)m[k]);
                const bool keep = (r >= 0) & (cl >= 0);
                rr[k]  = keep ? (float)r  : -1.0f;
                cc2[k] = keep ? (float)cl : -1.0f;
            }
            __stcs(&outr[e0 / 4],     make_float4(rr[0], rr[1], rr[2], rr[3]));
            __stcs(&outr[e0 / 4 + 1], make_float4(rr[4], rr[5], rr[6], rr[7]));
            __stcs(&outc[e0 / 4],     make_float4(cc2[0], cc2[1], cc2[2], cc2[3]));
            __stcs(&outc[e0 / 4 + 1], make_float4(cc2[4], cc2[5], cc2[6], cc2[7]));
        }
    }
}

extern "C" void kernel_launch(void* const* d_in, const int* in_sizes, int n_in,
                              void* d_out, int out_size) {
    const float* x        = (const float*)d_in[0];
    const unsigned int* e = (const unsigned int*)d_in[1];
    float* out            = (float*)d_out;

    static bool attr_set = false;
    if (!attr_set) {
        cudaFuncSetAttribute(stream_kernel,
                             cudaFuncAttributeMaxDynamicSharedMemorySize,
                             LUT_BYTES);
        attr_set = true;
    }

    select_kernel<<<NUM_GRAPHS, NPG>>>(out, e);
    stream_kernel<<<STREAM_GRID, 1024, LUT_BYTES>>>(
        (const float4*)x, e,
        (float4*)(out + X_OFF),
        (float4*)(out + EDGE_OFF),
        (float4*)(out + EDGE_OFF + NEDGE));
}